// round 1
// baseline (speedup 1.0000x reference)
#include <cuda_runtime.h>
#include <cstdint>
#include <cstddef>

#define DEV __device__ __forceinline__

// ---------- small PTX helpers ----------
DEV uint32_t f2tf(float f) {           // fp32 -> tf32 with round-to-nearest (unbiased!)
    uint32_t r;
    asm("cvt.rna.tf32.f32 %0, %1;" : "=r"(r) : "f"(f));
    return r;
}
DEV float fexp2(float x) {
    float r;
    asm("ex2.approx.f32 %0, %1;" : "=f"(r) : "f"(x));
    return r;
}
DEV void mma8(float c[4], const uint32_t a[4], uint32_t b0, uint32_t b1) {
    asm volatile(
        "mma.sync.aligned.m16n8k8.row.col.f32.tf32.tf32.f32 "
        "{%0,%1,%2,%3}, {%4,%5,%6,%7}, {%8,%9}, {%0,%1,%2,%3};\n"
        : "+f"(c[0]), "+f"(c[1]), "+f"(c[2]), "+f"(c[3])
        : "r"(a[0]), "r"(a[1]), "r"(a[2]), "r"(a[3]), "r"(b0), "r"(b1));
}

// ---------- scratch (no allocations allowed -> __device__ globals) ----------
#define MTOT 4096
#define DM   1024
__device__ float g_qk [MTOT * DM];
__device__ float g_v  [MTOT * DM];
__device__ float g_cqk[MTOT * DM];
__device__ float g_cv [MTOT * DM];
__device__ float g_o1 [MTOT * DM];
__device__ float g_o2 [MTOT * DM];
__device__ float g_y  [MTOT * DM];

// ============================================================================
// TF32 GEMM: C[M=4096,1024] = A[4096,1024] @ B[1024,1024] (+ Cin) (+ bias)
// 128x128x32 tile, 256 threads, warp grid 2x4 (each warp 64x32),
// register-prefetch over gmem, conflict-free smem frag loads.
// ============================================================================
#define AS_LD 36
#define BS_LD 136
#define GEMM_SMEM ((128 * AS_LD + 32 * BS_LD) * 4)

__global__ void __launch_bounds__(256) gemm_tf32(
    float* __restrict__ C, const float* __restrict__ A,
    const float* __restrict__ B, const float* __restrict__ Cin,
    const float* __restrict__ bias)
{
    extern __shared__ float sm[];
    float* As = sm;                 // [128][36]  (tf32 bits)
    float* Bs = sm + 128 * AS_LD;   // [32][136]

    const int bm = blockIdx.y << 7;
    const int bn = blockIdx.x << 7;
    const int tid = threadIdx.x;
    const int wid = tid >> 5, lane = tid & 31;
    const int qid = lane >> 2, qtr = lane & 3;
    const int wm = (wid >> 2) << 6;   // 0 / 64
    const int wn = (wid & 3) << 5;    // 0..96

    int ar[4], af4[4], br[4], bf4[4];
#pragma unroll
    for (int p = 0; p < 4; p++) {
        int idx = tid + (p << 8);
        ar[p] = idx >> 3; af4[p] = (idx & 7) << 2;    // A: 128 rows x 8 f4
        br[p] = idx >> 5; bf4[p] = (idx & 31) << 2;   // B: 32 rows x 32 f4
    }

    float acc[4][4][4];
#pragma unroll
    for (int mt = 0; mt < 4; mt++)
#pragma unroll
        for (int nt = 0; nt < 4; nt++)
#pragma unroll
            for (int r = 0; r < 4; r++) acc[mt][nt][r] = 0.f;

    float4 pa[4], pb[4];
#pragma unroll
    for (int p = 0; p < 4; p++) {
        pa[p] = *(const float4*)(A + (bm + ar[p]) * 1024 + af4[p]);
        pb[p] = *(const float4*)(B + br[p] * 1024 + bn + bf4[p]);
    }

    for (int kt = 0; kt < 32; kt++) {
        __syncthreads();
#pragma unroll
        for (int p = 0; p < 4; p++) {
            uint32_t* da = (uint32_t*)(As + ar[p] * AS_LD + af4[p]);
            da[0] = f2tf(pa[p].x); da[1] = f2tf(pa[p].y);
            da[2] = f2tf(pa[p].z); da[3] = f2tf(pa[p].w);
            uint32_t* db = (uint32_t*)(Bs + br[p] * BS_LD + bf4[p]);
            db[0] = f2tf(pb[p].x); db[1] = f2tf(pb[p].y);
            db[2] = f2tf(pb[p].z); db[3] = f2tf(pb[p].w);
        }
        __syncthreads();
        if (kt < 31) {
            int ka = (kt + 1) << 5;
#pragma unroll
            for (int p = 0; p < 4; p++) {
                pa[p] = *(const float4*)(A + (bm + ar[p]) * 1024 + ka + af4[p]);
                pb[p] = *(const float4*)(B + (ka + br[p]) * 1024 + bn + bf4[p]);
            }
        }
#pragma unroll
        for (int ks = 0; ks < 4; ks++) {
            uint32_t afr[4][4], bfr[4][2];
#pragma unroll
            for (int mt = 0; mt < 4; mt++) {
                const float* p0 = As + (wm + (mt << 4) + qid) * AS_LD + (ks << 3) + qtr;
                afr[mt][0] = *(const uint32_t*)(p0);
                afr[mt][1] = *(const uint32_t*)(p0 + 8 * AS_LD);
                afr[mt][2] = *(const uint32_t*)(p0 + 4);
                afr[mt][3] = *(const uint32_t*)(p0 + 8 * AS_LD + 4);
            }
#pragma unroll
            for (int nt = 0; nt < 4; nt++) {
                const float* p0 = Bs + ((ks << 3) + qtr) * BS_LD + wn + (nt << 3) + qid;
                bfr[nt][0] = *(const uint32_t*)(p0);
                bfr[nt][1] = *(const uint32_t*)(p0 + 4 * BS_LD);
            }
#pragma unroll
            for (int mt = 0; mt < 4; mt++)
#pragma unroll
                for (int nt = 0; nt < 4; nt++)
                    mma8(acc[mt][nt], afr[mt], bfr[nt][0], bfr[nt][1]);
        }
    }

    // epilogue
#pragma unroll
    for (int mt = 0; mt < 4; mt++) {
        int gr0 = bm + wm + (mt << 4) + qid;
#pragma unroll
        for (int nt = 0; nt < 4; nt++) {
            int gc = bn + wn + (nt << 3) + (qtr << 1);
            float2 v0 = make_float2(acc[mt][nt][0], acc[mt][nt][1]);
            float2 v1 = make_float2(acc[mt][nt][2], acc[mt][nt][3]);
            if (bias) {
                float2 bv = *(const float2*)(bias + gc);
                v0.x += bv.x; v0.y += bv.y; v1.x += bv.x; v1.y += bv.y;
            }
            if (Cin) {
                float2 c0 = *(const float2*)(Cin + (size_t)gr0 * 1024 + gc);
                float2 c1 = *(const float2*)(Cin + (size_t)(gr0 + 8) * 1024 + gc);
                v0.x += c0.x; v0.y += c0.y; v1.x += c1.x; v1.y += c1.y;
            }
            *(float2*)(C + (size_t)gr0 * 1024 + gc) = v0;
            *(float2*)(C + (size_t)(gr0 + 8) * 1024 + gc) = v1;
        }
    }
}

// ============================================================================
// Flash attention (one direction). O[i,:] = softmax_j(Q_i . K_j / 8) @ V
// Per CTA: 128 query rows of one (b,h). BC=64 key block. 256 threads / 8 warps,
// each warp owns 16 rows. All matmuls tf32 mma, online softmax in base-2 domain.
// ============================================================================
#define KS_LD 68
#define VS_LD 72
#define PS_LD 68
#define FLASH_SMEM ((64 * KS_LD + 64 * VS_LD + 128 * PS_LD) * 4)

__global__ void __launch_bounds__(256) flash_tf32(
    float* __restrict__ O, const float* __restrict__ Q,
    const float* __restrict__ Km, const float* __restrict__ Vm)
{
    extern __shared__ float sm[];
    float* Ks = sm;                  // [64][68]
    float* Vs = sm + 64 * KS_LD;     // [64][72]
    float* Ps = Vs + 64 * VS_LD;     // [128][68]

    const int tid = threadIdx.x;
    const int wid = tid >> 5, lane = tid & 31;
    const int qid = lane >> 2, qtr = lane & 3;
    const int cb   = blockIdx.y << 6;                       // head col base
    const int rowQ = (blockIdx.z << 10) + (blockIdx.x << 7);
    const int rowK = blockIdx.z << 10;

    // Q fragments (persistent in registers), direct gmem load
    uint32_t qa[8][4];
    {
        const float* qp = Q + (size_t)(rowQ + (wid << 4) + qid) * 1024 + cb;
#pragma unroll
        for (int ks = 0; ks < 8; ks++) {
            qa[ks][0] = f2tf(qp[(ks << 3) + qtr]);
            qa[ks][1] = f2tf(qp[8 * 1024 + (ks << 3) + qtr]);
            qa[ks][2] = f2tf(qp[(ks << 3) + qtr + 4]);
            qa[ks][3] = f2tf(qp[8 * 1024 + (ks << 3) + qtr + 4]);
        }
    }

    float m0 = -1e30f, m1 = -1e30f, l0 = 0.f, l1 = 0.f;
    float oc[8][4];
#pragma unroll
    for (int nt = 0; nt < 8; nt++)
#pragma unroll
        for (int r = 0; r < 4; r++) oc[nt][r] = 0.f;

    const float SL2E = 1.4426950408889634f * 0.125f;  // log2(e)/sqrt(DH)
    float* Pw = Ps + (wid << 4) * PS_LD;

    for (int jb = 0; jb < 16; jb++) {
        __syncthreads();   // all warps done with prev K/V/P before overwrite
#pragma unroll
        for (int p = 0; p < 4; p++) {
            int idx = tid + (p << 8);
            int r = idx >> 4, f4 = (idx & 15) << 2;
            size_t g = (size_t)(rowK + (jb << 6) + r) * 1024 + cb + f4;
            float4 kv = *(const float4*)(Km + g);
            uint32_t* dk = (uint32_t*)(Ks + r * KS_LD + f4);
            dk[0] = f2tf(kv.x); dk[1] = f2tf(kv.y); dk[2] = f2tf(kv.z); dk[3] = f2tf(kv.w);
            float4 vv = *(const float4*)(Vm + g);
            uint32_t* dv = (uint32_t*)(Vs + r * VS_LD + f4);
            dv[0] = f2tf(vv.x); dv[1] = f2tf(vv.y); dv[2] = f2tf(vv.z); dv[3] = f2tf(vv.w);
        }
        __syncthreads();

        // S = Q K^T  (16x64 per warp)
        float sc[8][4];
#pragma unroll
        for (int nt = 0; nt < 8; nt++)
#pragma unroll
            for (int r = 0; r < 4; r++) sc[nt][r] = 0.f;
#pragma unroll
        for (int ks = 0; ks < 8; ks++) {
#pragma unroll
            for (int nt = 0; nt < 8; nt++) {
                const float* kp = Ks + ((nt << 3) + qid) * KS_LD + (ks << 3) + qtr;
                mma8(sc[nt], qa[ks], *(const uint32_t*)kp, *(const uint32_t*)(kp + 4));
            }
        }

        // online softmax (log2 domain)
        float rm0 = -1e30f, rm1 = -1e30f;
#pragma unroll
        for (int nt = 0; nt < 8; nt++) {
            rm0 = fmaxf(rm0, fmaxf(sc[nt][0], sc[nt][1]));
            rm1 = fmaxf(rm1, fmaxf(sc[nt][2], sc[nt][3]));
        }
        rm0 = fmaxf(rm0, __shfl_xor_sync(0xffffffffu, rm0, 1));
        rm0 = fmaxf(rm0, __shfl_xor_sync(0xffffffffu, rm0, 2));
        rm1 = fmaxf(rm1, __shfl_xor_sync(0xffffffffu, rm1, 1));
        rm1 = fmaxf(rm1, __shfl_xor_sync(0xffffffffu, rm1, 2));
        float mn0 = fmaxf(m0, rm0 * SL2E);
        float mn1 = fmaxf(m1, rm1 * SL2E);
        float c0 = fexp2(m0 - mn0), c1 = fexp2(m1 - mn1);
        m0 = mn0; m1 = mn1;
        l0 *= c0; l1 *= c1;
        float ps0 = 0.f, ps1 = 0.f;
#pragma unroll
        for (int nt = 0; nt < 8; nt++) {
            oc[nt][0] *= c0; oc[nt][1] *= c0; oc[nt][2] *= c1; oc[nt][3] *= c1;
            float p0 = fexp2(fmaf(sc[nt][0], SL2E, -mn0));
            float p1 = fexp2(fmaf(sc[nt][1], SL2E, -mn0));
            float p2 = fexp2(fmaf(sc[nt][2], SL2E, -mn1));
            float p3 = fexp2(fmaf(sc[nt][3], SL2E, -mn1));
            ps0 += p0 + p1; ps1 += p2 + p3;
            *(uint2*)(Pw + qid * PS_LD + (nt << 3) + (qtr << 1)) =
                make_uint2(f2tf(p0), f2tf(p1));
            *(uint2*)(Pw + (qid + 8) * PS_LD + (nt << 3) + (qtr << 1)) =
                make_uint2(f2tf(p2), f2tf(p3));
        }
        l0 += ps0; l1 += ps1;
        __syncwarp();   // P tile is warp-private: warp-level fence is enough

        // O += P @ V
#pragma unroll
        for (int ks = 0; ks < 8; ks++) {
            uint32_t pfr[4];
            const float* pp = Pw + qid * PS_LD + (ks << 3) + qtr;
            pfr[0] = *(const uint32_t*)pp;
            pfr[1] = *(const uint32_t*)(pp + 8 * PS_LD);
            pfr[2] = *(const uint32_t*)(pp + 4);
            pfr[3] = *(const uint32_t*)(pp + 8 * PS_LD + 4);
#pragma unroll
            for (int nt = 0; nt < 8; nt++) {
                const float* vp = Vs + ((ks << 3) + qtr) * VS_LD + (nt << 3) + qid;
                mma8(oc[nt], pfr, *(const uint32_t*)vp, *(const uint32_t*)(vp + 4 * VS_LD));
            }
        }
    }

    // finalize: divide rows by l, write out in merged-head layout
    l0 += __shfl_xor_sync(0xffffffffu, l0, 1);
    l0 += __shfl_xor_sync(0xffffffffu, l0, 2);
    l1 += __shfl_xor_sync(0xffffffffu, l1, 1);
    l1 += __shfl_xor_sync(0xffffffffu, l1, 2);
    float inv0 = 1.0f / l0, inv1 = 1.0f / l1;
    float* op = O + (size_t)(rowQ + (wid << 4) + qid) * 1024 + cb;
#pragma unroll
    for (int nt = 0; nt < 8; nt++) {
        *(float2*)(op + (nt << 3) + (qtr << 1)) =
            make_float2(oc[nt][0] * inv0, oc[nt][1] * inv0);
        *(float2*)(op + 8 * 1024 + (nt << 3) + (qtr << 1)) =
            make_float2(oc[nt][2] * inv1, oc[nt][3] * inv1);
    }
}

// ============================================================================
// LayerNorm(Y) + x + context  (one row per CTA)
// ============================================================================
__global__ void __launch_bounds__(256) ln_residual(
    float* __restrict__ out, const float* __restrict__ Y,
    const float* __restrict__ x, const float* __restrict__ ctx,
    const float* __restrict__ gamma, const float* __restrict__ beta)
{
    __shared__ float rs[8], rs2[8];
    const int row = blockIdx.x;
    const int tid = threadIdx.x;
    const size_t base = (size_t)row << 10;
    float4 v = *(const float4*)(Y + base + (tid << 2));
    float s  = v.x + v.y + v.z + v.w;
    float s2 = v.x * v.x + v.y * v.y + v.z * v.z + v.w * v.w;
#pragma unroll
    for (int o = 16; o; o >>= 1) {
        s  += __shfl_xor_sync(0xffffffffu, s, o);
        s2 += __shfl_xor_sync(0xffffffffu, s2, o);
    }
    if ((tid & 31) == 0) { rs[tid >> 5] = s; rs2[tid >> 5] = s2; }
    __syncthreads();
    float tot = 0.f, tot2 = 0.f;
#pragma unroll
    for (int i = 0; i < 8; i++) { tot += rs[i]; tot2 += rs2[i]; }
    float mu  = tot * (1.f / 1024.f);
    float var = tot2 * (1.f / 1024.f) - mu * mu;
    float rstd = rsqrtf(var + 1e-5f);
    float4 g  = *(const float4*)(gamma + (tid << 2));
    float4 bb = *(const float4*)(beta + (tid << 2));
    float4 xr = *(const float4*)(x + base + (tid << 2));
    float4 cr = *(const float4*)(ctx + base + (tid << 2));
    float4 o;
    o.x = (v.x - mu) * rstd * g.x + bb.x + xr.x + cr.x;
    o.y = (v.y - mu) * rstd * g.y + bb.y + xr.y + cr.y;
    o.z = (v.z - mu) * rstd * g.z + bb.z + xr.z + cr.z;
    o.w = (v.w - mu) * rstd * g.w + bb.w + xr.w + cr.w;
    *(float4*)(out + base + (tid << 2)) = o;
}

// ============================================================================
// host
// ============================================================================
extern "C" void kernel_launch(void* const* d_in, const int* in_sizes, int n_in,
                              void* d_out, int out_size)
{
    (void)in_sizes; (void)n_in; (void)out_size;
    const float* x     = (const float*)d_in[0];
    const float* ctx   = (const float*)d_in[1];
    const float* Wqk   = (const float*)d_in[2];
    const float* Wcqk  = (const float*)d_in[3];
    const float* Wv    = (const float*)d_in[4];
    const float* Wcv   = (const float*)d_in[5];
    const float* Wout  = (const float*)d_in[6];
    const float* bout  = (const float*)d_in[7];
    const float* Wcout = (const float*)d_in[8];
    const float* bcout = (const float*)d_in[9];
    const float* gamma = (const float*)d_in[10];
    const float* beta  = (const float*)d_in[11];
    float* out = (float*)d_out;

    float *qk, *v, *cqk, *cv, *o1, *o2, *y;
    cudaGetSymbolAddress((void**)&qk,  g_qk);
    cudaGetSymbolAddress((void**)&v,   g_v);
    cudaGetSymbolAddress((void**)&cqk, g_cqk);
    cudaGetSymbolAddress((void**)&cv,  g_cv);
    cudaGetSymbolAddress((void**)&o1,  g_o1);
    cudaGetSymbolAddress((void**)&o2,  g_o2);
    cudaGetSymbolAddress((void**)&y,   g_y);

    cudaFuncSetAttribute(flash_tf32, cudaFuncAttributeMaxDynamicSharedMemorySize,
                         FLASH_SMEM);

    dim3 gg(8, 32);   // N/128, M/128
    gemm_tf32<<<gg, 256, GEMM_SMEM>>>(qk,  x,   Wqk,  nullptr, nullptr);
    gemm_tf32<<<gg, 256, GEMM_SMEM>>>(v,   x,   Wv,   nullptr, nullptr);
    gemm_tf32<<<gg, 256, GEMM_SMEM>>>(cqk, ctx, Wcqk, nullptr, nullptr);
    gemm_tf32<<<gg, 256, GEMM_SMEM>>>(cv,  ctx, Wcv,  nullptr, nullptr);

    dim3 gf(8, 16, 4);  // i-block, head, batch
    flash_tf32<<<gf, 256, FLASH_SMEM>>>(o1, qk,  cqk, cv);  // x attends context
    flash_tf32<<<gf, 256, FLASH_SMEM>>>(o2, cqk, qk,  v);   // context attends x

    gemm_tf32<<<gg, 256, GEMM_SMEM>>>(y, o1, Wout,  nullptr, bout);
    gemm_tf32<<<gg, 256, GEMM_SMEM>>>(y, o2, Wcout, y,       bcout);

    ln_residual<<<4096, 256>>>(out, y, x, ctx, gamma, beta);
}

// round 2
// speedup vs baseline: 1.3283x; 1.3283x over previous
#include <cuda_runtime.h>
#include <cstdint>
#include <cstddef>

#define DEV __device__ __forceinline__

// ---------------- PTX helpers ----------------
DEV uint32_t f2tf(float f) {            // fp32 -> tf32, round-to-nearest
    uint32_t r;
    asm("cvt.rna.tf32.f32 %0, %1;" : "=r"(r) : "f"(f));
    return r;
}
DEV float rndf(float f) { return __uint_as_float(f2tf(f)); }
DEV float fexp2(float x) {
    float r;
    asm("ex2.approx.f32 %0, %1;" : "=f"(r) : "f"(x));
    return r;
}
DEV void mma8(float c[4], const uint32_t a[4], uint32_t b0, uint32_t b1) {
    asm volatile(
        "mma.sync.aligned.m16n8k8.row.col.f32.tf32.tf32.f32 "
        "{%0,%1,%2,%3}, {%4,%5,%6,%7}, {%8,%9}, {%0,%1,%2,%3};\n"
        : "+f"(c[0]), "+f"(c[1]), "+f"(c[2]), "+f"(c[3])
        : "r"(a[0]), "r"(a[1]), "r"(a[2]), "r"(a[3]), "r"(b0), "r"(b1));
}
DEV void cp16(uint32_t dst, const void* src) {
    asm volatile("cp.async.cg.shared.global [%0], [%1], 16;\n"
                 :: "r"(dst), "l"(src));
}
DEV void cp_commit() { asm volatile("cp.async.commit_group;\n" ::: "memory"); }
template <int N> DEV void cp_wait() {
    asm volatile("cp.async.wait_group %0;\n" :: "n"(N) : "memory");
}

// ---------------- scratch ----------------
#define MTOT 4096
#define DM   1024
__device__ float g_qk [MTOT * DM];
__device__ float g_v  [MTOT * DM];
__device__ float g_cqk[MTOT * DM];
__device__ float g_cv [MTOT * DM];
__device__ float g_o1 [MTOT * DM];
__device__ float g_o2 [MTOT * DM];
__device__ float g_y  [MTOT * DM];
__device__ float g_xr [MTOT * DM];
__device__ float g_cr [MTOT * DM];
__device__ float g_wr [6 * DM * DM];
__device__ float g_bs [DM];

// ============================================================================
// Pre-pass: tf32-round x, ctx, 6 weights; sum the two output biases.
// ============================================================================
__global__ void __launch_bounds__(256) prepass(
    const float* __restrict__ x,    const float* __restrict__ ctx,
    const float* __restrict__ wqk,  const float* __restrict__ wv,
    const float* __restrict__ wcqk, const float* __restrict__ wcv,
    const float* __restrict__ wout, const float* __restrict__ wcout,
    const float* __restrict__ bout, const float* __restrict__ bcout,
    float* __restrict__ xr, float* __restrict__ cr,
    float* __restrict__ wr, float* __restrict__ bs)
{
    const long bid = blockIdx.x;
    const int tid = threadIdx.x;
    if (bid == 14336) {                    // bias sum block
        float4 a = ((const float4*)bout)[tid];
        float4 b = ((const float4*)bcout)[tid];
        ((float4*)bs)[tid] = make_float4(a.x + b.x, a.y + b.y, a.z + b.z, a.w + b.w);
        return;
    }
    long id = bid * 256 + tid;             // float4 index
    const float4* src; float4* dst;
    if (id < 1048576)       { src = (const float4*)x   + id;           dst = (float4*)xr + id; }
    else if (id < 2097152)  { src = (const float4*)ctx + (id-1048576); dst = (float4*)cr + (id-1048576); }
    else {
        long off = id - 2097152;
        long w = off >> 18;
        long wo = off & 262143;
        const float* ws;
        switch ((int)w) {
            case 0: ws = wqk;  break;  case 1: ws = wv;   break;
            case 2: ws = wcqk; break;  case 3: ws = wcv;  break;
            case 4: ws = wout; break;  default: ws = wcout; break;
        }
        src = (const float4*)ws + wo;
        dst = (float4*)wr + off;
    }
    float4 a = *src;
    *dst = make_float4(rndf(a.x), rndf(a.y), rndf(a.z), rndf(a.w));
}

// ============================================================================
// TF32 GEMM core: 128x128 tile, 3-stage cp.async pipeline, 256 thr / 8 warps.
// Supports dual K-segment (C = A0@B0 + A1@B1) + bias + optional tf32-rounded out.
// ============================================================================
#define AS_LD 36
#define BS_LD 136
#define STG_F (128 * AS_LD + 32 * BS_LD)        // 8960 floats / stage
#define GEMM_SMEM (3 * STG_F * 4)               // 107520 B

DEV void gemm_load_stage(uint32_t sa, const float* __restrict__ A,
                         const float* __restrict__ B, int bm, int bn, int kk,
                         int arow, int ac4, int brow, int bc4)
{
    uint32_t sb = sa + 128 * AS_LD * 4;
#pragma unroll
    for (int p = 0; p < 4; p++) {
        int r = arow + (p << 5);
        cp16(sa + (uint32_t)(r * AS_LD + ac4) * 4,
             A + (size_t)(bm + r) * 1024 + kk + ac4);
        int rb = brow + (p << 3);
        cp16(sb + (uint32_t)(rb * BS_LD + bc4) * 4,
             B + (size_t)(kk + rb) * 1024 + bn + bc4);
    }
}

DEV void gemm_core(float* __restrict__ C,
                   const float* __restrict__ A0, const float* __restrict__ B0,
                   const float* __restrict__ A1, const float* __restrict__ B1,
                   const float* __restrict__ bias, int nkt, int round_out,
                   int bm, int bn)
{
    extern __shared__ float sm[];
    const uint32_t sbase = (uint32_t)__cvta_generic_to_shared(sm);
    const int tid = threadIdx.x;
    const int wid = tid >> 5, lane = tid & 31;
    const int qid = lane >> 2, qtr = lane & 3;
    const int wm = (wid >> 2) << 6;
    const int wn = (wid & 3) << 5;

    const int arow = tid >> 3, ac4 = (tid & 7) << 2;
    const int brow = tid >> 5, bc4 = (tid & 31) << 2;

    float acc[4][4][4];
#pragma unroll
    for (int mt = 0; mt < 4; mt++)
#pragma unroll
        for (int nt = 0; nt < 4; nt++)
#pragma unroll
            for (int r = 0; r < 4; r++) acc[mt][nt][r] = 0.f;

    // prologue: stages 0,1
#pragma unroll
    for (int s = 0; s < 2; s++) {
        const float* A = (s < 32 || !A1) ? A0 : A1;
        const float* B = (s < 32 || !B1) ? B0 : B1;
        gemm_load_stage(sbase + s * STG_F * 4, A, B, bm, bn, (s & 31) << 5,
                        arow, ac4, brow, bc4);
        cp_commit();
    }

    for (int kt = 0; kt < nkt; kt++) {
        cp_wait<1>();
        __syncthreads();
        int L = kt + 2;
        if (L < nkt) {
            const float* A = (L < 32) ? A0 : A1;
            const float* B = (L < 32) ? B0 : B1;
            int s = L >= 3 ? L - 3 * ((L * 0x5556) >> 16) : L; // L % 3
            s = L % 3;
            gemm_load_stage(sbase + (uint32_t)s * STG_F * 4, A, B, bm, bn,
                            (L & 31) << 5, arow, ac4, brow, bc4);
        }
        cp_commit();

        const float* As = sm + (kt % 3) * STG_F;
        const float* Bs = As + 128 * AS_LD;
#pragma unroll
        for (int ks = 0; ks < 4; ks++) {
            uint32_t afr[4][4], bfr[4][2];
#pragma unroll
            for (int mt = 0; mt < 4; mt++) {
                const float* p0 = As + (wm + (mt << 4) + qid) * AS_LD + (ks << 3) + qtr;
                afr[mt][0] = *(const uint32_t*)(p0);
                afr[mt][1] = *(const uint32_t*)(p0 + 8 * AS_LD);
                afr[mt][2] = *(const uint32_t*)(p0 + 4);
                afr[mt][3] = *(const uint32_t*)(p0 + 8 * AS_LD + 4);
            }
#pragma unroll
            for (int nt = 0; nt < 4; nt++) {
                const float* p0 = Bs + ((ks << 3) + qtr) * BS_LD + wn + (nt << 3) + qid;
                bfr[nt][0] = *(const uint32_t*)(p0);
                bfr[nt][1] = *(const uint32_t*)(p0 + 4 * BS_LD);
            }
#pragma unroll
            for (int mt = 0; mt < 4; mt++)
#pragma unroll
                for (int nt = 0; nt < 4; nt++)
                    mma8(acc[mt][nt], afr[mt], bfr[nt][0], bfr[nt][1]);
        }
    }

    // epilogue
#pragma unroll
    for (int mt = 0; mt < 4; mt++) {
        int gr0 = bm + wm + (mt << 4) + qid;
#pragma unroll
        for (int nt = 0; nt < 4; nt++) {
            int gc = bn + wn + (nt << 3) + (qtr << 1);
            float2 v0 = make_float2(acc[mt][nt][0], acc[mt][nt][1]);
            float2 v1 = make_float2(acc[mt][nt][2], acc[mt][nt][3]);
            if (bias) {
                float2 bv = *(const float2*)(bias + gc);
                v0.x += bv.x; v0.y += bv.y; v1.x += bv.x; v1.y += bv.y;
            }
            if (round_out) {
                v0.x = rndf(v0.x); v0.y = rndf(v0.y);
                v1.x = rndf(v1.x); v1.y = rndf(v1.y);
            }
            *(float2*)(C + (size_t)gr0 * 1024 + gc) = v0;
            *(float2*)(C + (size_t)(gr0 + 8) * 1024 + gc) = v1;
        }
    }
}

// all 4 projection GEMMs in one launch (z selects)
__global__ void __launch_bounds__(256, 2) proj_gemm(
    float* __restrict__ qk, float* __restrict__ v,
    float* __restrict__ cqk, float* __restrict__ cv,
    const float* __restrict__ xr, const float* __restrict__ cr,
    const float* __restrict__ wr)
{
    const int z = blockIdx.z;
    const float* A = (z < 2) ? xr : cr;
    const float* B = wr + (size_t)z * 1048576;   // order: wqk, wv, wcqk, wcv
    float* C = (z == 0) ? qk : (z == 1) ? v : (z == 2) ? cqk : cv;
    gemm_core(C, A, B, nullptr, nullptr, nullptr, 32, 1,
              blockIdx.y << 7, blockIdx.x << 7);
}

// y = o1 @ Wout + o2 @ Wcout + (bout + bcout)
__global__ void __launch_bounds__(256, 2) out_gemm(
    float* __restrict__ y, const float* __restrict__ o1,
    const float* __restrict__ o2, const float* __restrict__ wr,
    const float* __restrict__ bs)
{
    gemm_core(y, o1, wr + 4ll * 1048576, o2, wr + 5ll * 1048576, bs, 64, 0,
              blockIdx.y << 7, blockIdx.x << 7);
}

// ============================================================================
// Flash attention, both directions in one launch. Double-buffered cp.async K/V.
// ============================================================================
#define KS_LD 68
#define VS_LD 72
#define PS_LD 68
#define KV_STG_F (64 * KS_LD + 64 * VS_LD)       // 8960 floats
#define FLASH_SMEM ((2 * KV_STG_F + 128 * PS_LD) * 4)

__global__ void __launch_bounds__(256) flash_tf32(
    float* __restrict__ o1, float* __restrict__ o2,
    const float* __restrict__ qk, const float* __restrict__ cqk,
    const float* __restrict__ vv_, const float* __restrict__ cv_)
{
    extern __shared__ float sm[];
    const uint32_t sbase = (uint32_t)__cvta_generic_to_shared(sm);
    float* Ps = sm + 2 * KV_STG_F;

    const int tid = threadIdx.x;
    const int wid = tid >> 5, lane = tid & 31;
    const int qid = lane >> 2, qtr = lane & 3;
    const int dir = blockIdx.z >> 2, bz = blockIdx.z & 3;
    const float* Q = dir ? cqk : qk;
    const float* K = dir ? qk  : cqk;
    const float* V = dir ? vv_ : cv_;
    float* O       = dir ? o2  : o1;

    const int cb   = blockIdx.y << 6;
    const int rowQ = (bz << 10) + (blockIdx.x << 7);
    const int rowK = bz << 10;

    const int kvr = tid >> 4, kvc4 = (tid & 15) << 2;

    // Q fragments (values already tf32-rounded -> raw bits)
    uint32_t qa[8][4];
    {
        const float* qp = Q + (size_t)(rowQ + (wid << 4) + qid) * 1024 + cb;
#pragma unroll
        for (int ks = 0; ks < 8; ks++) {
            qa[ks][0] = __float_as_uint(qp[(ks << 3) + qtr]);
            qa[ks][1] = __float_as_uint(qp[8 * 1024 + (ks << 3) + qtr]);
            qa[ks][2] = __float_as_uint(qp[(ks << 3) + qtr + 4]);
            qa[ks][3] = __float_as_uint(qp[8 * 1024 + (ks << 3) + qtr + 4]);
        }
    }

    // prologue load jb=0 into stage 0
    {
        uint32_t sk = sbase, sv = sbase + 64 * KS_LD * 4;
#pragma unroll
        for (int p = 0; p < 4; p++) {
            int r = kvr + (p << 4);
            size_t g = (size_t)(rowK + r) * 1024 + cb + kvc4;
            cp16(sk + (uint32_t)(r * KS_LD + kvc4) * 4, K + g);
            cp16(sv + (uint32_t)(r * VS_LD + kvc4) * 4, V + g);
        }
        cp_commit();
    }

    float m0 = -1e30f, m1 = -1e30f, l0 = 0.f, l1 = 0.f;
    float oc[8][4];
#pragma unroll
    for (int nt = 0; nt < 8; nt++)
#pragma unroll
        for (int r = 0; r < 4; r++) oc[nt][r] = 0.f;

    const float SL2E = 1.4426950408889634f * 0.125f;
    float* Pw = Ps + (wid << 4) * PS_LD;

    for (int jb = 0; jb < 16; jb++) {
        __syncthreads();                 // prev compute done with next-stage buffer
        if (jb + 1 < 16) {
            uint32_t sb2 = sbase + (uint32_t)((jb + 1) & 1) * KV_STG_F * 4;
            uint32_t sk = sb2, sv = sb2 + 64 * KS_LD * 4;
#pragma unroll
            for (int p = 0; p < 4; p++) {
                int r = kvr + (p << 4);
                size_t g = (size_t)(rowK + ((jb + 1) << 6) + r) * 1024 + cb + kvc4;
                cp16(sk + (uint32_t)(r * KS_LD + kvc4) * 4, K + g);
                cp16(sv + (uint32_t)(r * VS_LD + kvc4) * 4, V + g);
            }
        }
        cp_commit();
        cp_wait<1>();
        __syncthreads();

        const float* Ks = sm + (jb & 1) * KV_STG_F;
        const float* Vs = Ks + 64 * KS_LD;

        // S = Q K^T (16x64 per warp)
        float sc[8][4];
#pragma unroll
        for (int nt = 0; nt < 8; nt++)
#pragma unroll
            for (int r = 0; r < 4; r++) sc[nt][r] = 0.f;
#pragma unroll
        for (int ks = 0; ks < 8; ks++) {
#pragma unroll
            for (int nt = 0; nt < 8; nt++) {
                const float* kp = Ks + ((nt << 3) + qid) * KS_LD + (ks << 3) + qtr;
                mma8(sc[nt], qa[ks], *(const uint32_t*)kp, *(const uint32_t*)(kp + 4));
            }
        }

        // online softmax (base-2)
        float rm0 = -1e30f, rm1 = -1e30f;
#pragma unroll
        for (int nt = 0; nt < 8; nt++) {
            rm0 = fmaxf(rm0, fmaxf(sc[nt][0], sc[nt][1]));
            rm1 = fmaxf(rm1, fmaxf(sc[nt][2], sc[nt][3]));
        }
        rm0 = fmaxf(rm0, __shfl_xor_sync(0xffffffffu, rm0, 1));
        rm0 = fmaxf(rm0, __shfl_xor_sync(0xffffffffu, rm0, 2));
        rm1 = fmaxf(rm1, __shfl_xor_sync(0xffffffffu, rm1, 1));
        rm1 = fmaxf(rm1, __shfl_xor_sync(0xffffffffu, rm1, 2));
        float mn0 = fmaxf(m0, rm0 * SL2E);
        float mn1 = fmaxf(m1, rm1 * SL2E);
        float c0 = fexp2(m0 - mn0), c1 = fexp2(m1 - mn1);
        m0 = mn0; m1 = mn1;
        l0 *= c0; l1 *= c1;
        float ps0 = 0.f, ps1 = 0.f;
#pragma unroll
        for (int nt = 0; nt < 8; nt++) {
            oc[nt][0] *= c0; oc[nt][1] *= c0; oc[nt][2] *= c1; oc[nt][3] *= c1;
            float p0 = fexp2(fmaf(sc[nt][0], SL2E, -mn0));
            float p1 = fexp2(fmaf(sc[nt][1], SL2E, -mn0));
            float p2 = fexp2(fmaf(sc[nt][2], SL2E, -mn1));
            float p3 = fexp2(fmaf(sc[nt][3], SL2E, -mn1));
            ps0 += p0 + p1; ps1 += p2 + p3;
            *(uint2*)(Pw + qid * PS_LD + (nt << 3) + (qtr << 1)) =
                make_uint2(f2tf(p0), f2tf(p1));
            *(uint2*)(Pw + (qid + 8) * PS_LD + (nt << 3) + (qtr << 1)) =
                make_uint2(f2tf(p2), f2tf(p3));
        }
        l0 += ps0; l1 += ps1;
        __syncwarp();                  // P tile is warp-private

        // O += P @ V
#pragma unroll
        for (int ks = 0; ks < 8; ks++) {
            uint32_t pfr[4];
            const float* pp = Pw + qid * PS_LD + (ks << 3) + qtr;
            pfr[0] = *(const uint32_t*)pp;
            pfr[1] = *(const uint32_t*)(pp + 8 * PS_LD);
            pfr[2] = *(const uint32_t*)(pp + 4);
            pfr[3] = *(const uint32_t*)(pp + 8 * PS_LD + 4);
#pragma unroll
            for (int nt = 0; nt < 8; nt++) {
                const float* vp = Vs + ((ks << 3) + qtr) * VS_LD + (nt << 3) + qid;
                mma8(oc[nt], pfr, *(const uint32_t*)vp, *(const uint32_t*)(vp + 4 * VS_LD));
            }
        }
    }

    // finalize (output tf32-rounded: feeds out_gemm via cp.async)
    l0 += __shfl_xor_sync(0xffffffffu, l0, 1);
    l0 += __shfl_xor_sync(0xffffffffu, l0, 2);
    l1 += __shfl_xor_sync(0xffffffffu, l1, 1);
    l1 += __shfl_xor_sync(0xffffffffu, l1, 2);
    float inv0 = 1.0f / l0, inv1 = 1.0f / l1;
    float* op = O + (size_t)(rowQ + (wid << 4) + qid) * 1024 + cb;
#pragma unroll
    for (int nt = 0; nt < 8; nt++) {
        *(float2*)(op + (nt << 3) + (qtr << 1)) =
            make_float2(rndf(oc[nt][0] * inv0), rndf(oc[nt][1] * inv0));
        *(float2*)(op + 8 * 1024 + (nt << 3) + (qtr << 1)) =
            make_float2(rndf(oc[nt][2] * inv1), rndf(oc[nt][3] * inv1));
    }
}

// ============================================================================
// LayerNorm(Y) + x + context
// ============================================================================
__global__ void __launch_bounds__(256) ln_residual(
    float* __restrict__ out, const float* __restrict__ Y,
    const float* __restrict__ x, const float* __restrict__ ctx,
    const float* __restrict__ gamma, const float* __restrict__ beta)
{
    __shared__ float rs[8], rs2[8];
    const int row = blockIdx.x;
    const int tid = threadIdx.x;
    const size_t base = (size_t)row << 10;
    float4 v = *(const float4*)(Y + base + (tid << 2));
    float s  = v.x + v.y + v.z + v.w;
    float s2 = v.x * v.x + v.y * v.y + v.z * v.z + v.w * v.w;
#pragma unroll
    for (int o = 16; o; o >>= 1) {
        s  += __shfl_xor_sync(0xffffffffu, s, o);
        s2 += __shfl_xor_sync(0xffffffffu, s2, o);
    }
    if ((tid & 31) == 0) { rs[tid >> 5] = s; rs2[tid >> 5] = s2; }
    __syncthreads();
    float tot = 0.f, tot2 = 0.f;
#pragma unroll
    for (int i = 0; i < 8; i++) { tot += rs[i]; tot2 += rs2[i]; }
    float mu  = tot * (1.f / 1024.f);
    float var = tot2 * (1.f / 1024.f) - mu * mu;
    float rstd = rsqrtf(var + 1e-5f);
    float4 g  = *(const float4*)(gamma + (tid << 2));
    float4 bb = *(const float4*)(beta + (tid << 2));
    float4 xr = *(const float4*)(x + base + (tid << 2));
    float4 cr = *(const float4*)(ctx + base + (tid << 2));
    float4 o;
    o.x = (v.x - mu) * rstd * g.x + bb.x + xr.x + cr.x;
    o.y = (v.y - mu) * rstd * g.y + bb.y + xr.y + cr.y;
    o.z = (v.z - mu) * rstd * g.z + bb.z + xr.z + cr.z;
    o.w = (v.w - mu) * rstd * g.w + bb.w + xr.w + cr.w;
    *(float4*)(out + base + (tid << 2)) = o;
}

// ============================================================================
// host
// ============================================================================
extern "C" void kernel_launch(void* const* d_in, const int* in_sizes, int n_in,
                              void* d_out, int out_size)
{
    (void)in_sizes; (void)n_in; (void)out_size;
    const float* x     = (const float*)d_in[0];
    const float* ctx   = (const float*)d_in[1];
    const float* Wqk   = (const float*)d_in[2];
    const float* Wcqk  = (const float*)d_in[3];
    const float* Wv    = (const float*)d_in[4];
    const float* Wcv   = (const float*)d_in[5];
    const float* Wout  = (const float*)d_in[6];
    const float* bout  = (const float*)d_in[7];
    const float* Wcout = (const float*)d_in[8];
    const float* bcout = (const float*)d_in[9];
    const float* gamma = (const float*)d_in[10];
    const float* beta  = (const float*)d_in[11];
    float* out = (float*)d_out;

    float *qk, *v, *cqk, *cv, *o1, *o2, *y, *xr, *cr, *wr, *bs;
    cudaGetSymbolAddress((void**)&qk,  g_qk);
    cudaGetSymbolAddress((void**)&v,   g_v);
    cudaGetSymbolAddress((void**)&cqk, g_cqk);
    cudaGetSymbolAddress((void**)&cv,  g_cv);
    cudaGetSymbolAddress((void**)&o1,  g_o1);
    cudaGetSymbolAddress((void**)&o2,  g_o2);
    cudaGetSymbolAddress((void**)&y,   g_y);
    cudaGetSymbolAddress((void**)&xr,  g_xr);
    cudaGetSymbolAddress((void**)&cr,  g_cr);
    cudaGetSymbolAddress((void**)&wr,  g_wr);
    cudaGetSymbolAddress((void**)&bs,  g_bs);

    cudaFuncSetAttribute(proj_gemm, cudaFuncAttributeMaxDynamicSharedMemorySize, GEMM_SMEM);
    cudaFuncSetAttribute(out_gemm,  cudaFuncAttributeMaxDynamicSharedMemorySize, GEMM_SMEM);
    cudaFuncSetAttribute(flash_tf32, cudaFuncAttributeMaxDynamicSharedMemorySize, FLASH_SMEM);

    prepass<<<14337, 256>>>(x, ctx, Wqk, Wv, Wcqk, Wcv, Wout, Wcout,
                            bout, bcout, xr, cr, wr, bs);

    proj_gemm<<<dim3(8, 32, 4), 256, GEMM_SMEM>>>(qk, v, cqk, cv, xr, cr, wr);

    flash_tf32<<<dim3(8, 16, 8), 256, FLASH_SMEM>>>(o1, o2, qk, cqk, v, cv);

    out_gemm<<<dim3(8, 32), 256, GEMM_SMEM>>>(y, o1, o2, wr, bs);

    ln_residual<<<4096, 256>>>(out, y, x, ctx, gamma, beta);
}